// round 10
// baseline (speedup 1.0000x reference)
#include <cuda_runtime.h>
#include <cstddef>

// GazeLSTM on GB300 (sm_103a). B=16384, T=128, half=64.
// Single kernel, 32-thread (1-warp) blocks:
//  * blocks [0, nback): backward chain + FUSED LSTM. WH/bias in registers
//    (critical path), WI via volatile SMEM loads per step (anti-hoist: keeps
//    regs < 255, no spills). Writes rows 0..half-1 and row half.
//  * blocks [nback, ..): forward chain. Writes rows half+1..T-1.

#define BT  32      // b's per block (one warp)
#define C   8       // matrices per chunk
#define NQ  18      // float4 per b per chain chunk

__device__ __forceinline__ unsigned long long pk2(float lo, float hi) {
    unsigned long long r; asm("mov.b64 %0, {%1, %2};" : "=l"(r) : "f"(lo), "f"(hi)); return r;
}
__device__ __forceinline__ void upk2(float& lo, float& hi, unsigned long long v) {
    asm("mov.b64 {%0, %1}, %2;" : "=f"(lo), "=f"(hi) : "l"(v));
}
__device__ __forceinline__ unsigned long long fma2(unsigned long long a, unsigned long long b, unsigned long long c) {
    unsigned long long d; asm("fma.rn.f32x2 %0, %1, %2, %3;" : "=l"(d) : "l"(a), "l"(b), "l"(c)); return d;
}
__device__ __forceinline__ float tanhx(float x) {
    float y; asm("tanh.approx.f32 %0, %1;" : "=f"(y) : "f"(x)); return y;
}

#define CP16(dst_u32, src_ptr) \
    asm volatile("cp.async.cg.shared.global [%0], [%1], 16;" :: "r"(dst_u32), "l"(src_ptr))
#define CP_COMMIT() asm volatile("cp.async.commit_group;")
#define CP_WAIT1()  asm volatile("cp.async.wait_group 1;")
#define CP_WAIT0()  asm volatile("cp.async.wait_group 0;")

// Stage chain chunk: 32 b's x NQ quads, 18 CP16/thread. j0 % 4 == 0 required.
__device__ __forceinline__ void stage_chain(float4* __restrict__ sdst,
                                            const float4* __restrict__ src4base,
                                            int t9q, int tid) {
    int bp = tid / NQ;
    int q  = tid - bp * NQ;
#pragma unroll
    for (int k = 0; k < NQ; k++) {
        const float4* src = src4base + (size_t)bp * t9q + q;
        unsigned dst = (unsigned)__cvta_generic_to_shared(sdst + q * BT + (bp ^ q));
        CP16(dst, src);
        q += 14; bp += 1;                 // advance 32 = 1*18 + 14
        if (q >= NQ) { q -= NQ; bp += 1; }
    }
}

template <int M>
__device__ __forceinline__ void loadA(float* A, const float4* __restrict__ buf, int tid) {
    constexpr int F0 = 9 * M, QA = F0 >> 2, OFF = F0 & 3;
    float tmp[12];
    *(float4*)(tmp + 0) = buf[(QA + 0) * BT + (tid ^ (QA + 0))];
    *(float4*)(tmp + 4) = buf[(QA + 1) * BT + (tid ^ (QA + 1))];
    *(float4*)(tmp + 8) = buf[(QA + 2) * BT + (tid ^ (QA + 2))];
#pragma unroll
    for (int i = 0; i < 9; i++) A[i] = tmp[OFF + i];
}

// Coalesced writeback: NF floats/b for 32 b's from swizzled sout.
template <int NF>
__device__ __forceinline__ void store_chain(float* __restrict__ gdst, size_t T3,
                                            const float* __restrict__ sout, int tid) {
    int bp = tid / NF;
    int e  = tid - bp * NF;
    constexpr int DB = BT / NF;
    constexpr int DE = BT % NF;
#pragma unroll
    for (int k = 0; k < NF; k++) {
        gdst[(size_t)bp * T3 + e] = sout[e * BT + (bp ^ e)];
        bp += DB; e += DE;
        if (e >= NF) { e -= NF; bp += 1; }
    }
}

// LSTM step: WH/BS in registers (h critical path), WI via VOLATILE smem loads
// (anti-hoist). Weights prescaled: sigmoid gates x0.5; sig(x)=0.5+0.5*tanh(x/2).
// vWI layout: WI[p][j] at index p*3+j (18 u64).
#define LSTM_STEP_V(x0, x1, x2)                                                      \
    do {                                                                             \
        unsigned long long xx0 = pk2((x0), (x0)), xx1 = pk2((x1), (x1)), xx2 = pk2((x2), (x2)); \
        unsigned long long hh0 = pk2(h0, h0), hh1 = pk2(h1, h1), hh2 = pk2(h2, h2);  \
        float th[12];                                                                \
        _Pragma("unroll") for (int p = 0; p < 6; p++) {                              \
            unsigned long long wi0 = vWI[p * 3 + 0];                                 \
            unsigned long long wi1 = vWI[p * 3 + 1];                                 \
            unsigned long long wi2 = vWI[p * 3 + 2];                                 \
            unsigned long long xp = fma2(wi0, xx0, fma2(wi1, xx1, fma2(wi2, xx2, BS[p]))); \
            unsigned long long g  = fma2(WH[p][0], hh0, fma2(WH[p][1], hh1, fma2(WH[p][2], hh2, xp))); \
            float a_, b_; upk2(a_, b_, g);                                           \
            th[2 * p] = tanhx(a_); th[2 * p + 1] = tanhx(b_);                        \
        }                                                                            \
        float i0 = fmaf(0.5f, th[0], 0.5f), i1 = fmaf(0.5f, th[1], 0.5f), i2 = fmaf(0.5f, th[2], 0.5f); \
        float f0 = fmaf(0.5f, th[3], 0.5f), f1 = fmaf(0.5f, th[4], 0.5f), f2 = fmaf(0.5f, th[5], 0.5f); \
        float o0 = fmaf(0.5f, th[9], 0.5f), o1 = fmaf(0.5f, th[10], 0.5f), o2 = fmaf(0.5f, th[11], 0.5f); \
        c0 = fmaf(f0, c0, i0 * th[6]);                                               \
        c1 = fmaf(f1, c1, i1 * th[7]);                                               \
        c2 = fmaf(f2, c2, i2 * th[8]);                                               \
        h0 = o0 * tanhx(c0); h1 = o1 * tanhx(c1); h2 = o2 * tanhx(c2);               \
    } while (0)

__global__ __launch_bounds__(BT) void gaze_kernel(
    const float* __restrict__ dir, const float* __restrict__ R,
    const float* __restrict__ Wih, const float* __restrict__ Whh,
    const float* __restrict__ bih, const float* __restrict__ bhh,
    float* __restrict__ out, int B, int T, int nback)
{
    __shared__ float4 sbuf[2][NQ * BT];           // 2 x 9216 B
    __shared__ float  sout[3 * C * BT];           // 3072 B
    __shared__ unsigned long long swi[18];        // WI packed (fused blocks only)

    const int half = T >> 1;
    const int t9q = (T * 9) >> 2;
    const size_t T3 = (size_t)T * 3;
    const int tid = threadIdx.x;
    const int nchunks = half / C;                 // 8

    if ((int)blockIdx.x < nback) {
        // ============ fused backward chain + LSTM: 32 b's ============
        const int bbase = blockIdx.x * BT;

        // SMEM WI init: 6 threads, one gate-pair each (prescaled).
        if (tid < 6) {
            const int p = tid, g0 = 2 * p, g1 = 2 * p + 1;
            const float s0 = (g0 >= 6 && g0 <= 8) ? 1.0f : 0.5f;
            const float s1 = (g1 >= 6 && g1 <= 8) ? 1.0f : 0.5f;
#pragma unroll
            for (int j = 0; j < 3; j++)
                swi[p * 3 + j] = pk2(__ldg(Wih + g0 * 3 + j) * s0, __ldg(Wih + g1 * 3 + j) * s1);
        }
        const volatile unsigned long long* vWI = swi;

        // WH + bias in registers (on the serial h critical path).
        unsigned long long WH[6][3], BS[6];
#pragma unroll
        for (int p = 0; p < 6; p++) {
            const int g0 = 2 * p, g1 = 2 * p + 1;
            const float s0 = (g0 >= 6 && g0 <= 8) ? 1.0f : 0.5f;
            const float s1 = (g1 >= 6 && g1 <= 8) ? 1.0f : 0.5f;
#pragma unroll
            for (int j = 0; j < 3; j++)
                WH[p][j] = pk2(__ldg(Whh + g0 * 3 + j) * s0, __ldg(Whh + g1 * 3 + j) * s1);
            BS[p] = pk2((__ldg(bih + g0) + __ldg(bhh + g0)) * s0,
                        (__ldg(bih + g1) + __ldg(bhh + g1)) * s1);
        }

        const float d0 = __ldg(dir + (size_t)(bbase + tid) * 3 + 0);
        const float d1 = __ldg(dir + (size_t)(bbase + tid) * 3 + 1);
        const float d2 = __ldg(dir + (size_t)(bbase + tid) * 3 + 2);
        float v0 = d0, v1 = d1, v2 = d2;
        float h0 = 0.f, h1 = 0.f, h2 = 0.f, c0 = 0.f, c1 = 0.f, c2 = 0.f;

        const float4* R4 = (const float4*)R + (size_t)bbase * t9q;
        float* oblk = out + (size_t)bbase * T3;

        stage_chain(sbuf[0], R4 + (((half - C) * 9) >> 2), t9q, tid);
        CP_COMMIT();
        __syncwarp();                              // WI visible

        for (int cc = 0; cc < nchunks; cc++) {
            if (cc + 1 < nchunks) {
                stage_chain(sbuf[(cc + 1) & 1], R4 + (((half - C * (cc + 2)) * 9) >> 2), t9q, tid);
                CP_COMMIT(); CP_WAIT1();
            } else CP_WAIT0();
            __syncwarp();

            const float4* buf = sbuf[cc & 1];
#pragma unroll
            for (int s = 0; s < C; s++) {
                float A[9];
                switch (s) {   // matrix slot 7-s (reverse within chunk) => t ascending
                    case 0: loadA<7>(A, buf, tid); break;
                    case 1: loadA<6>(A, buf, tid); break;
                    case 2: loadA<5>(A, buf, tid); break;
                    case 3: loadA<4>(A, buf, tid); break;
                    case 4: loadA<3>(A, buf, tid); break;
                    case 5: loadA<2>(A, buf, tid); break;
                    case 6: loadA<1>(A, buf, tid); break;
                    default: loadA<0>(A, buf, tid); break;
                }
                // v = A^T v
                float n0 = fmaf(A[6], v2, fmaf(A[3], v1, A[0] * v0));
                float n1 = fmaf(A[7], v2, fmaf(A[4], v1, A[1] * v0));
                float n2 = fmaf(A[8], v2, fmaf(A[5], v1, A[2] * v0));
                v0 = n0; v1 = n1; v2 = n2;
                const int eo = 3 * s;
                sout[(eo + 0) * BT + (tid ^ (eo + 0))] = v0;
                sout[(eo + 1) * BT + (tid ^ (eo + 1))] = v1;
                sout[(eo + 2) * BT + (tid ^ (eo + 2))] = v2;

                LSTM_STEP_V(v0, v1, v2);           // consumes x_t = dirs[8cc+s]
            }
            __syncwarp();
            store_chain<3 * C>(oblk + (size_t)(C * cc) * 3, T3, sout, tid);
            __syncwarp();
        }

        // final LSTM step consumes dir; h is the output row at t = half
        LSTM_STEP_V(d0, d1, d2);
        float* ob = out + (size_t)(bbase + tid) * T3 + (size_t)half * 3;
        ob[0] = h0; ob[1] = h1; ob[2] = h2;
    } else {
        // ============ forward chain: 32 b's (R8/R9-proven) ============
        const int bbase = ((int)blockIdx.x - nback) * BT;
        const int nsteps = T - 1 - half;           // 63

        float v0 = __ldg(dir + (size_t)(bbase + tid) * 3 + 0);
        float v1 = __ldg(dir + (size_t)(bbase + tid) * 3 + 1);
        float v2 = __ldg(dir + (size_t)(bbase + tid) * 3 + 2);

        const float4* R4 = (const float4*)R + (size_t)bbase * t9q;
        float* oblk = out + (size_t)bbase * T3;

        stage_chain(sbuf[0], R4 + ((half * 9) >> 2), t9q, tid);
        CP_COMMIT();
        for (int cc = 0; cc < nchunks; cc++) {
            if (cc + 1 < nchunks) {
                stage_chain(sbuf[(cc + 1) & 1], R4 + (((half + C * (cc + 1)) * 9) >> 2), t9q, tid);
                CP_COMMIT(); CP_WAIT1();
            } else CP_WAIT0();
            __syncwarp();

            const float4* buf = sbuf[cc & 1];
            const int ns = (nsteps - C * cc) < C ? (nsteps - C * cc) : C;
#pragma unroll
            for (int s = 0; s < C; s++) {
                if (s < ns) {
                    float A[9];
                    switch (s) {
                        case 0: loadA<0>(A, buf, tid); break;
                        case 1: loadA<1>(A, buf, tid); break;
                        case 2: loadA<2>(A, buf, tid); break;
                        case 3: loadA<3>(A, buf, tid); break;
                        case 4: loadA<4>(A, buf, tid); break;
                        case 5: loadA<5>(A, buf, tid); break;
                        case 6: loadA<6>(A, buf, tid); break;
                        default: loadA<7>(A, buf, tid); break;
                    }
                    // v = A v
                    float n0 = fmaf(A[2], v2, fmaf(A[1], v1, A[0] * v0));
                    float n1 = fmaf(A[5], v2, fmaf(A[4], v1, A[3] * v0));
                    float n2 = fmaf(A[8], v2, fmaf(A[7], v1, A[6] * v0));
                    v0 = n0; v1 = n1; v2 = n2;
                    const int eo = 3 * s;
                    sout[(eo + 0) * BT + (tid ^ (eo + 0))] = v0;
                    sout[(eo + 1) * BT + (tid ^ (eo + 1))] = v1;
                    sout[(eo + 2) * BT + (tid ^ (eo + 2))] = v2;
                }
            }
            __syncwarp();
            float* gdst = oblk + (size_t)(half + 1 + C * cc) * 3;
            if (ns == C) store_chain<3 * C>(gdst, T3, sout, tid);
            else         store_chain<21>(gdst, T3, sout, tid);   // last: 7 steps
            __syncwarp();
        }
    }
}

extern "C" void kernel_launch(void* const* d_in, const int* in_sizes, int n_in,
                              void* d_out, int out_size)
{
    const float* dir = (const float*)d_in[0];
    const float* R   = (const float*)d_in[1];
    const float* Wih = (const float*)d_in[2];
    const float* Whh = (const float*)d_in[3];
    const float* bih = (const float*)d_in[4];
    const float* bhh = (const float*)d_in[5];
    float* out = (float*)d_out;

    const int B = in_sizes[0] / 3;
    const int T = in_sizes[1] / (B * 9);
    const int nback = B / BT;   // 512
    const int nfwd  = B / BT;   // 512

    gaze_kernel<<<nback + nfwd, BT>>>(dir, R, Wih, Whh, bih, bhh, out, B, T, nback);
}